// round 6
// baseline (speedup 1.0000x reference)
#include <cuda_runtime.h>
#include <math_constants.h>

#define NTRK 4096
#define NB 64
#define NBINS (NB * NB)
#define FULLMASK 0xffffffffu
#define BUILD_THREADS 1024
#define SEARCH_WARPS 8
#define SEARCH_THREADS (SEARCH_WARPS * 32)

// ---- device scratch (static: no allocation) ----
__device__ float4 g_par0;            // minx, miny, invx, invy
__device__ float2 g_par1;            // cwx, cwy
__device__ int    g_ofs[NBINS + 1];
__device__ float4 g_pk[NTRK];        // packed sorted points: x, y, bits(pid), 0

// lexicographic (d2, idx) insert into sorted-4 list; exact top_k tie-break
#define LESSI(da, ja, db, jb) (((da) < (db)) || ((da) == (db) && (ja) < (jb)))
#define LEX_INSERT(dv, jv)                                         \
    if (LESSI(dv, jv, s3, i3)) {                                   \
        if (LESSI(dv, jv, s1, i1)) {                               \
            s3 = s2; i3 = i2; s2 = s1; i2 = i1;                    \
            if (LESSI(dv, jv, s0, i0)) { s1 = s0; i1 = i0; s0 = (dv); i0 = (jv); } \
            else                       { s1 = (dv); i1 = (jv); }   \
        } else {                                                   \
            if (LESSI(dv, jv, s2, i2)) { s3 = s2; i3 = i2; s2 = (dv); i2 = (jv); } \
            else                       { s3 = (dv); i3 = (jv); }   \
        }                                                          \
    }

// coalesced lane-parallel scan of a contiguous sorted-point span
#define PROC_SPAN(bg, en)                                          \
    for (int p_ = (bg) + lane; p_ < (en); p_ += 32) {              \
        float4 t_ = g_pk[p_];                                      \
        int pj_ = __float_as_int(t_.z);                            \
        float dx_ = t_.x - qx, dy_ = t_.y - qy;                    \
        float dd_ = fmaf(dx_, dx_, dy_ * dy_);                     \
        if (pj_ != i) { LEX_INSERT(dd_, pj_); }                    \
    }

// one window row [xa..xb] of cells == one contiguous span
#define PROC_ROW(yy, xa, xb)                                       \
    do {                                                           \
        int r_ = (yy) * NB;                                        \
        int bg_ = g_ofs[r_ + (xa)];                                \
        int en_ = g_ofs[r_ + (xb) + 1];                            \
        PROC_SPAN(bg_, en_);                                       \
    } while (0)

// ============================================================================
// Kernel 1: fused grid build (1 block) — bbox, histogram, 2-level scan, scatter
// ============================================================================
__global__ __launch_bounds__(BUILD_THREADS)
void build_kernel(const float2* __restrict__ obs2, int n)
{
    __shared__ int   s_cnt[NBINS];          // histogram -> cursors
    __shared__ int   s_wsum[32];            // warp scan totals
    __shared__ float s_red[128];            // bbox reduce scratch
    __shared__ float s_par[4];

    const int t    = threadIdx.x;
    const int lane = t & 31;
    const int warp = t >> 5;

    float px[4], py[4];
    float mnx = CUDART_INF_F, mxx = -CUDART_INF_F;
    float mny = CUDART_INF_F, mxy = -CUDART_INF_F;
    #pragma unroll
    for (int k = 0; k < 4; ++k) {
        int p = t + k * BUILD_THREADS;
        px[k] = 0.f; py[k] = 0.f;
        if (p < n) {
            float2 v = obs2[p];
            px[k] = v.x; py[k] = v.y;
            mnx = fminf(mnx, v.x); mxx = fmaxf(mxx, v.x);
            mny = fminf(mny, v.y); mxy = fmaxf(mxy, v.y);
        }
    }

    #pragma unroll
    for (int off = 16; off > 0; off >>= 1) {
        mnx = fminf(mnx, __shfl_xor_sync(FULLMASK, mnx, off));
        mxx = fmaxf(mxx, __shfl_xor_sync(FULLMASK, mxx, off));
        mny = fminf(mny, __shfl_xor_sync(FULLMASK, mny, off));
        mxy = fmaxf(mxy, __shfl_xor_sync(FULLMASK, mxy, off));
    }
    if (lane == 0) {
        s_red[warp]      = mnx;
        s_red[32 + warp] = mxx;
        s_red[64 + warp] = mny;
        s_red[96 + warp] = mxy;
    }
    for (int c = t; c < NBINS; c += BUILD_THREADS) s_cnt[c] = 0;
    __syncthreads();

    if (warp == 0) {
        float a  = s_red[lane];
        float b_ = s_red[32 + lane];
        float c  = s_red[64 + lane];
        float d  = s_red[96 + lane];
        #pragma unroll
        for (int off = 16; off > 0; off >>= 1) {
            a  = fminf(a,  __shfl_xor_sync(FULLMASK, a,  off));
            b_ = fmaxf(b_, __shfl_xor_sync(FULLMASK, b_, off));
            c  = fminf(c,  __shfl_xor_sync(FULLMASK, c,  off));
            d  = fmaxf(d,  __shfl_xor_sync(FULLMASK, d,  off));
        }
        if (lane == 0) {
            float wx = fmaxf(b_ - a, 1e-30f);
            float wy = fmaxf(d - c, 1e-30f);
            float invx = (float)NB / wx, invy = (float)NB / wy;
            g_par0 = make_float4(a, c, invx, invy);
            g_par1 = make_float2(wx / (float)NB, wy / (float)NB);
            s_par[0] = a; s_par[1] = c; s_par[2] = invx; s_par[3] = invy;
        }
    }
    __syncthreads();

    const float minx = s_par[0], miny = s_par[1];
    const float invx = s_par[2], invy = s_par[3];

    int bins[4] = {0, 0, 0, 0};
    #pragma unroll
    for (int k = 0; k < 4; ++k) {
        int p = t + k * BUILD_THREADS;
        if (p < n) {
            int bx = min(NB - 1, max(0, (int)((px[k] - minx) * invx)));
            int by = min(NB - 1, max(0, (int)((py[k] - miny) * invy)));
            bins[k] = by * NB + bx;
            atomicAdd(&s_cnt[bins[k]], 1);
        }
    }
    __syncthreads();

    // 2-level warp-shuffle exclusive scan over 4096 bins (4/thread)
    int c4[4];
    #pragma unroll
    for (int k = 0; k < 4; ++k) c4[k] = s_cnt[4 * t + k];
    int tot = c4[0] + c4[1] + c4[2] + c4[3];
    int incl = tot;
    #pragma unroll
    for (int off = 1; off < 32; off <<= 1) {
        int v = __shfl_up_sync(FULLMASK, incl, off);
        if (lane >= off) incl += v;
    }
    if (lane == 31) s_wsum[warp] = incl;
    __syncthreads();
    if (warp == 0) {
        int v = s_wsum[lane];
        int wi = v;
        #pragma unroll
        for (int off = 1; off < 32; off <<= 1) {
            int u = __shfl_up_sync(FULLMASK, wi, off);
            if (lane >= off) wi += u;
        }
        s_wsum[lane] = wi - v;   // exclusive warp base
    }
    __syncthreads();

    int run = s_wsum[warp] + (incl - tot);
    int cur[4];
    #pragma unroll
    for (int k = 0; k < 4; ++k) {
        g_ofs[4 * t + k] = run;
        cur[k] = run;
        run += c4[k];
    }
    if (t == BUILD_THREADS - 1) g_ofs[NBINS] = run;
    __syncthreads();
    #pragma unroll
    for (int k = 0; k < 4; ++k) s_cnt[4 * t + k] = cur[k];
    __syncthreads();

    #pragma unroll
    for (int k = 0; k < 4; ++k) {
        int p = t + k * BUILD_THREADS;
        if (p < n) {
            int pos = atomicAdd(&s_cnt[bins[k]], 1);
            g_pk[pos] = make_float4(px[k], py[k], __int_as_float(p), 0.0f);
        }
    }
}

// ============================================================================
// Kernel 2: warp per SORTED slot — rect-window kNN via coalesced row spans
// ============================================================================
__global__ __launch_bounds__(SEARCH_THREADS)
void search_kernel(const float2* __restrict__ obs1,
                   const float2* __restrict__ obs2,
                   const float* __restrict__ W,
                   const float* __restrict__ bias,
                   float* __restrict__ out,
                   int n)
{
    const int lane = threadIdx.x & 31;
    const int s = blockIdx.x * SEARCH_WARPS + (threadIdx.x >> 5);
    if (s >= n) return;

    const float4 me = g_pk[s];
    const float qx = me.x, qy = me.y;
    const int i = __float_as_int(me.z);

    const float4 par0 = g_par0;
    const float2 par1 = g_par1;
    const float minx = par0.x, miny = par0.y;
    const float invx = par0.z, invy = par0.w;
    const float cwx  = par1.x, cwy  = par1.y;

    const int cx = min(NB - 1, max(0, (int)((qx - minx) * invx)));
    const int cy = min(NB - 1, max(0, (int)((qy - miny) * invy)));

    float s0 = CUDART_INF_F, s1 = CUDART_INF_F, s2 = CUDART_INF_F, s3 = CUDART_INF_F;
    int   i0 = n, i1 = n, i2 = n, i3 = n;

    // initial 3x3 rect (clamped), processed as up-to-3 coalesced row spans
    int x0 = max(cx - 1, 0), x1 = min(cx + 1, NB - 1);
    int y0 = max(cy - 1, 0), y1 = min(cy + 1, NB - 1);
    for (int y = y0; y <= y1; ++y) PROC_ROW(y, x0, x1);

    const float eps = (cwx + cwy) * 0.001f;   // binning-rounding safety
    while (true) {
        // min distance from q to region outside the processed rect;
        // sides at the grid edge contribute +inf (no unprocessed points there)
        float bl = (x0 > 0)      ? (qx - (minx + (float)x0 * cwx))       : CUDART_INF_F;
        float br = (x1 < NB - 1) ? ((minx + (float)(x1 + 1) * cwx) - qx) : CUDART_INF_F;
        float bd = (y0 > 0)      ? (qy - (miny + (float)y0 * cwy))       : CUDART_INF_F;
        float bu = (y1 < NB - 1) ? ((miny + (float)(y1 + 1) * cwy) - qy) : CUDART_INF_F;
        float bmin = fminf(fminf(bl, br), fminf(bd, bu));

        if (isinf(bmin)) break;   // rect covers entire grid

        float be = fmaxf(bmin - eps, 0.0f);
        float b2 = be * be;
        // exact: >=4 candidates (disjoint across lanes) with d2 <= b2
        int cnt = (s3 <= b2) ? 4 : (s2 <= b2) ? 3 : (s1 <= b2) ? 2 : (s0 <= b2) ? 1 : 0;
        if (__reduce_add_sync(FULLMASK, cnt) >= 4) break;

        // expand rect by 1 in every non-clamped direction; process new cells
        int nx0 = max(x0 - 1, 0), nx1 = min(x1 + 1, NB - 1);
        int ny0 = max(y0 - 1, 0), ny1 = min(y1 + 1, NB - 1);
        if (ny0 < y0) PROC_ROW(ny0, nx0, nx1);            // new top row
        if (ny1 > y1) PROC_ROW(ny1, nx0, nx1);            // new bottom row
        if (nx0 < x0) for (int y = y0; y <= y1; ++y) PROC_ROW(y, nx0, x0 - 1);
        if (nx1 > x1) for (int y = y0; y <= y1; ++y) PROC_ROW(y, x1 + 1, nx1);
        x0 = nx0; x1 = nx1; y0 = ny0; y1 = ny1;
    }

    // butterfly merge: every lane ends with identical global top-4
    #pragma unroll
    for (int off = 16; off > 0; off >>= 1) {
        float t0 = __shfl_xor_sync(FULLMASK, s0, off);
        float t1 = __shfl_xor_sync(FULLMASK, s1, off);
        float t2 = __shfl_xor_sync(FULLMASK, s2, off);
        float t3 = __shfl_xor_sync(FULLMASK, s3, off);
        int   u0 = __shfl_xor_sync(FULLMASK, i0, off);
        int   u1 = __shfl_xor_sync(FULLMASK, i1, off);
        int   u2 = __shfl_xor_sync(FULLMASK, i2, off);
        int   u3 = __shfl_xor_sync(FULLMASK, i3, off);
        LEX_INSERT(t0, u0);
        LEX_INSERT(t1, u1);
        LEX_INSERT(t2, u2);
        LEX_INSERT(t3, u3);
    }

    // epilogue: lane = k*8 + e computes out[i][k*8 + e]
    const int k = lane >> 3;
    const int e = lane & 7;
    int nj = (k == 0) ? i0 : (k == 1) ? i1 : (k == 2) ? i2 : i3;
    if (nj >= n) nj = (i == 0) ? 1 : 0;   // degenerate-n safety

    float2 pj  = obs2[nj];
    float2 o1j = obs1[nj];
    float2 o1i = obs1[i];

    float rpx = pj.x - qx;
    float rpy = pj.y - qy;
    float rvx = (pj.x - o1j.x) - (qx - o1i.x);
    float rvy = (pj.y - o1j.y) - (qy - o1i.y);

    float acc = bias[e];
    acc = fmaf(rpx, W[0 * 8 + e], acc);
    acc = fmaf(rpy, W[1 * 8 + e], acc);
    acc = fmaf(rvx, W[2 * 8 + e], acc);
    acc = fmaf(rvy, W[3 * 8 + e], acc);

    out[i * 32 + lane] = fmaxf(acc, 0.0f);
}

extern "C" void kernel_launch(void* const* d_in, const int* in_sizes, int n_in,
                              void* d_out, int out_size) {
    const float2* obs1 = (const float2*)d_in[0];  // [N, 2]
    const float2* obs2 = (const float2*)d_in[1];  // [N, 2]
    const float*  W    = (const float*)d_in[2];   // [4, 8]
    const float*  b    = (const float*)d_in[3];   // [8]
    float* out = (float*)d_out;                    // [N, 32]

    int n = in_sizes[0] / 2;
    if (n > NTRK) n = NTRK;

    build_kernel<<<1, BUILD_THREADS>>>(obs2, n);
    int blocks = (n + SEARCH_WARPS - 1) / SEARCH_WARPS;
    search_kernel<<<blocks, SEARCH_THREADS>>>(obs1, obs2, W, b, out, n);
}

// round 7
// speedup vs baseline: 1.7121x; 1.7121x over previous
#include <cuda_runtime.h>
#include <math_constants.h>

#define NTRK 4096
#define NB 64
#define NBINS (NB * NB)
#define FULLMASK 0xffffffffu
#define THREADS 1024
#define TRACKS_PER_BLOCK 32

// fixed bbox (exact for any input via clamping; see bound argument in PROC)
#define BB_MIN (-6.0f)
#define BB_W   (12.0f)
#define CW     (BB_W / (float)NB)        // 0.1875, exact in fp32
#define INVW   ((float)NB / BB_W)

// dynamic smem layout
#define SM_PTS_OFF  0                          // float2[4096]  = 32768
#define SM_OFS_OFF  32768                      // int[4097]     = 16388
#define SM_PID_OFF  (32768 + 16400)            // int[4096]     = 16384
#define SM_WSUM_OFF (32768 + 16400 + 16384)    // int[32]       = 128
#define SM_TOTAL    (32768 + 16400 + 16384 + 128)

// lexicographic (d2, idx) insert into sorted-4 list; exact top_k tie-break
#define LESSI(da, ja, db, jb) (((da) < (db)) || ((da) == (db) && (ja) < (jb)))
#define LEX_INSERT(dv, jv)                                         \
    if (LESSI(dv, jv, s3, i3)) {                                   \
        if (LESSI(dv, jv, s1, i1)) {                               \
            s3 = s2; i3 = i2; s2 = s1; i2 = i1;                    \
            if (LESSI(dv, jv, s0, i0)) { s1 = s0; i1 = i0; s0 = (dv); i0 = (jv); } \
            else                       { s1 = (dv); i1 = (jv); }   \
        } else {                                                   \
            if (LESSI(dv, jv, s2, i2)) { s3 = s2; i3 = i2; s2 = (dv); i2 = (jv); } \
            else                       { s3 = (dv); i3 = (jv); }   \
        }                                                          \
    }

// lane-parallel scan of a contiguous sorted-point span (all in SMEM)
#define PROC_SPAN(bg, en)                                          \
    for (int p_ = (bg) + lane; p_ < (en); p_ += 32) {              \
        float2 t_ = s_pts[p_];                                     \
        int pj_ = s_pid[p_];                                       \
        float dx_ = t_.x - qx, dy_ = t_.y - qy;                    \
        float dd_ = fmaf(dx_, dx_, dy_ * dy_);                     \
        if (pj_ != i) { LEX_INSERT(dd_, pj_); }                    \
    }

// one window row [xa..xb] of cells == one contiguous span
#define PROC_ROW(yy, xa, xb)                                       \
    do {                                                           \
        int r_ = (yy) * NB;                                        \
        int bg_ = s_ofs[r_ + (xa)];                                \
        int en_ = s_ofs[r_ + (xb) + 1];                            \
        PROC_SPAN(bg_, en_);                                       \
    } while (0)

__global__ __launch_bounds__(THREADS)
void nn_pool_fused(const float2* __restrict__ obs1,
                   const float2* __restrict__ obs2,
                   const float* __restrict__ W,
                   const float* __restrict__ bias,
                   float* __restrict__ out,
                   int n)
{
    extern __shared__ char smem_raw[];
    float2* s_pts  = (float2*)(smem_raw + SM_PTS_OFF);
    int*    s_ofs  = (int*)   (smem_raw + SM_OFS_OFF);   // [NBINS+1]
    int*    s_pid  = (int*)   (smem_raw + SM_PID_OFF);
    int*    s_wsum = (int*)   (smem_raw + SM_WSUM_OFF);

    const int t    = threadIdx.x;
    const int lane = t & 31;
    const int warp = t >> 5;

    // ---------------- per-block grid build (all in SMEM) ----------------
    // zero counts (counts live at s_ofs[1+b]; s_ofs[0] stays 0)
    for (int c = t; c < NBINS + 1; c += THREADS) s_ofs[c] = 0;
    __syncthreads();

    // load 4 points/thread, bin with fixed bbox + clamp, histogram
    float px[4], py[4];
    int   bins[4];
    #pragma unroll
    for (int k = 0; k < 4; ++k) {
        int p = t + k * THREADS;
        bins[k] = -1;
        if (p < n) {
            float2 v = obs2[p];
            px[k] = v.x; py[k] = v.y;
            int bx = min(NB - 1, max(0, (int)((v.x - BB_MIN) * INVW)));
            int by = min(NB - 1, max(0, (int)((v.y - BB_MIN) * INVW)));
            bins[k] = by * NB + bx;
            atomicAdd(&s_ofs[1 + bins[k]], 1);
        }
    }
    __syncthreads();

    // 2-level warp-shuffle exclusive scan over 4096 counts (4/thread)
    int c4[4];
    #pragma unroll
    for (int k = 0; k < 4; ++k) c4[k] = s_ofs[1 + 4 * t + k];
    int tot = c4[0] + c4[1] + c4[2] + c4[3];
    int incl = tot;
    #pragma unroll
    for (int off = 1; off < 32; off <<= 1) {
        int v = __shfl_up_sync(FULLMASK, incl, off);
        if (lane >= off) incl += v;
    }
    if (lane == 31) s_wsum[warp] = incl;
    __syncthreads();
    if (warp == 0) {
        int v = s_wsum[lane];
        int wi = v;
        #pragma unroll
        for (int off = 1; off < 32; off <<= 1) {
            int u = __shfl_up_sync(FULLMASK, wi, off);
            if (lane >= off) wi += u;
        }
        s_wsum[lane] = wi - v;   // exclusive warp base
    }
    __syncthreads();

    // write cursors: s_ofs[1+b] = excl[b]; after scatter it becomes excl[b+1],
    // so the final table satisfies s_ofs[b] = excl[b] for all b in [0, NBINS].
    int run = s_wsum[warp] + (incl - tot);
    #pragma unroll
    for (int k = 0; k < 4; ++k) {
        s_ofs[1 + 4 * t + k] = run;
        run += c4[k];
    }
    __syncthreads();

    // scatter into sorted smem arrays
    #pragma unroll
    for (int k = 0; k < 4; ++k) {
        if (bins[k] >= 0) {
            int pos = atomicAdd(&s_ofs[1 + bins[k]], 1);
            s_pts[pos] = make_float2(px[k], py[k]);
            s_pid[pos] = t + k * THREADS;
        }
    }
    __syncthreads();

    // ---------------- search: one warp per track, all SMEM ----------------
    const int i = blockIdx.x * TRACKS_PER_BLOCK + warp;
    if (i >= n) return;

    const float2 q = obs2[i];
    const float qx = q.x, qy = q.y;

    const int cx = min(NB - 1, max(0, (int)((qx - BB_MIN) * INVW)));
    const int cy = min(NB - 1, max(0, (int)((qy - BB_MIN) * INVW)));

    float s0 = CUDART_INF_F, s1 = CUDART_INF_F, s2 = CUDART_INF_F, s3 = CUDART_INF_F;
    int   i0 = n, i1 = n, i2 = n, i3 = n;

    // initial 3x3 rect (clamped)
    int x0 = max(cx - 1, 0), x1 = min(cx + 1, NB - 1);
    int y0 = max(cy - 1, 0), y1 = min(cy + 1, NB - 1);
    for (int y = y0; y <= y1; ++y) PROC_ROW(y, x0, x1);

    const float eps = CW * 0.002f;   // binning fp-rounding safety margin
    while (true) {
        // lower bound on distance to any unprocessed point. Grid-edge sides
        // contribute +inf: all points (incl. clamped outliers) live in bins
        // 0..NB-1, and a clamped outlier is farther out than its bin's
        // nominal region, so interior-side bounds remain valid lower bounds.
        float bl = (x0 > 0)      ? (qx - (BB_MIN + (float)x0 * CW))       : CUDART_INF_F;
        float br = (x1 < NB - 1) ? ((BB_MIN + (float)(x1 + 1) * CW) - qx) : CUDART_INF_F;
        float bd = (y0 > 0)      ? (qy - (BB_MIN + (float)y0 * CW))       : CUDART_INF_F;
        float bu = (y1 < NB - 1) ? ((BB_MIN + (float)(y1 + 1) * CW) - qy) : CUDART_INF_F;
        float bmin = fminf(fminf(bl, br), fminf(bd, bu));

        if (isinf(bmin)) break;   // rect covers entire grid

        float be = fmaxf(bmin - eps, 0.0f);
        float b2 = be * be;
        // exact termination: >=4 candidates (disjoint across lanes) with d2<=b2
        int cnt = (s3 <= b2) ? 4 : (s2 <= b2) ? 3 : (s1 <= b2) ? 2 : (s0 <= b2) ? 1 : 0;
        if (__reduce_add_sync(FULLMASK, cnt) >= 4) break;

        // expand rect by 1 in every non-clamped direction; process new cells
        int nx0 = max(x0 - 1, 0), nx1 = min(x1 + 1, NB - 1);
        int ny0 = max(y0 - 1, 0), ny1 = min(y1 + 1, NB - 1);
        if (ny0 < y0) PROC_ROW(ny0, nx0, nx1);
        if (ny1 > y1) PROC_ROW(ny1, nx0, nx1);
        if (nx0 < x0) for (int y = y0; y <= y1; ++y) PROC_ROW(y, nx0, x0 - 1);
        if (nx1 > x1) for (int y = y0; y <= y1; ++y) PROC_ROW(y, x1 + 1, nx1);
        x0 = nx0; x1 = nx1; y0 = ny0; y1 = ny1;
    }

    // butterfly merge: every lane ends with identical global top-4
    #pragma unroll
    for (int off = 16; off > 0; off >>= 1) {
        float t0 = __shfl_xor_sync(FULLMASK, s0, off);
        float t1 = __shfl_xor_sync(FULLMASK, s1, off);
        float t2 = __shfl_xor_sync(FULLMASK, s2, off);
        float t3 = __shfl_xor_sync(FULLMASK, s3, off);
        int   u0 = __shfl_xor_sync(FULLMASK, i0, off);
        int   u1 = __shfl_xor_sync(FULLMASK, i1, off);
        int   u2 = __shfl_xor_sync(FULLMASK, i2, off);
        int   u3 = __shfl_xor_sync(FULLMASK, i3, off);
        LEX_INSERT(t0, u0);
        LEX_INSERT(t1, u1);
        LEX_INSERT(t2, u2);
        LEX_INSERT(t3, u3);
    }

    // epilogue: lane = k*8 + e computes out[i][k*8 + e]
    const int k = lane >> 3;
    const int e = lane & 7;
    int nj = (k == 0) ? i0 : (k == 1) ? i1 : (k == 2) ? i2 : i3;
    if (nj >= n) nj = (i == 0) ? 1 : 0;   // degenerate-n safety

    float2 pj  = obs2[nj];
    float2 o1j = obs1[nj];
    float2 o1i = obs1[i];

    float rpx = pj.x - qx;
    float rpy = pj.y - qy;
    float rvx = (pj.x - o1j.x) - (qx - o1i.x);
    float rvy = (pj.y - o1j.y) - (qy - o1i.y);

    float acc = bias[e];
    acc = fmaf(rpx, W[0 * 8 + e], acc);
    acc = fmaf(rpy, W[1 * 8 + e], acc);
    acc = fmaf(rvx, W[2 * 8 + e], acc);
    acc = fmaf(rvy, W[3 * 8 + e], acc);

    out[i * 32 + lane] = fmaxf(acc, 0.0f);
}

extern "C" void kernel_launch(void* const* d_in, const int* in_sizes, int n_in,
                              void* d_out, int out_size) {
    const float2* obs1 = (const float2*)d_in[0];  // [N, 2]
    const float2* obs2 = (const float2*)d_in[1];  // [N, 2]
    const float*  W    = (const float*)d_in[2];   // [4, 8]
    const float*  b    = (const float*)d_in[3];   // [8]
    float* out = (float*)d_out;                    // [N, 32]

    int n = in_sizes[0] / 2;
    if (n > NTRK) n = NTRK;

    static bool attr_set = false;
    if (!attr_set) {
        cudaFuncSetAttribute(nn_pool_fused,
                             cudaFuncAttributeMaxDynamicSharedMemorySize,
                             SM_TOTAL);
        attr_set = true;
    }

    int blocks = (n + TRACKS_PER_BLOCK - 1) / TRACKS_PER_BLOCK;
    nn_pool_fused<<<blocks, THREADS, SM_TOTAL>>>(obs1, obs2, W, b, out, n);
}

// round 8
// speedup vs baseline: 2.0829x; 1.2166x over previous
#include <cuda_runtime.h>
#include <math_constants.h>

#define NTRK 4096
#define NB 64
#define NBINS (NB * NB)
#define FULLMASK 0xffffffffu
#define THREADS 1024
#define TRACKS_PER_BLOCK 32

// fixed bbox (exact for any input via clamping; bound argument below)
#define BB_MIN (-6.0f)
#define BB_W   (12.0f)
#define CW     (BB_W / (float)NB)        // 0.1875, exact in fp32
#define INVW   ((float)NB / BB_W)
#define EPSB   0.0005f                   // fp safety margin (>> any rounding here)

// dynamic smem layout
#define SM_PTS_OFF  0                          // float2[4096]  = 32768
#define SM_OFS_OFF  32768                      // int[4097]     = 16388
#define SM_PID_OFF  (32768 + 16400)            // int[4096]     = 16384
#define SM_WSUM_OFF (32768 + 16400 + 16384)    // int[32]       = 128
#define SM_TOTAL    (32768 + 16400 + 16384 + 128)

// lexicographic (d2, idx) insert into sorted-4 list; exact top_k tie-break.
// Fully order-independent, so any cell/lane processing order is exact.
#define LESSI(da, ja, db, jb) (((da) < (db)) || ((da) == (db) && (ja) < (jb)))
#define LEX_INSERT(dv, jv)                                         \
    if (LESSI(dv, jv, s3, i3)) {                                   \
        if (LESSI(dv, jv, s1, i1)) {                               \
            s3 = s2; i3 = i2; s2 = s1; i2 = i1;                    \
            if (LESSI(dv, jv, s0, i0)) { s1 = s0; i1 = i0; s0 = (dv); i0 = (jv); } \
            else                       { s1 = (dv); i1 = (jv); }   \
        } else {                                                   \
            if (LESSI(dv, jv, s2, i2)) { s3 = s2; i3 = i2; s2 = (dv); i2 = (jv); } \
            else                       { s3 = (dv); i3 = (jv); }   \
        }                                                          \
    }

// per-lane serial scan of a contiguous sorted-point span (SMEM)
#define SCAN_SPAN(bg, en)                                          \
    for (int p_ = (bg); p_ < (en); ++p_) {                         \
        float2 t_ = s_pts[p_];                                     \
        int pj_ = s_pid[p_];                                       \
        float dx_ = t_.x - qx, dy_ = t_.y - qy;                    \
        float dd_ = fmaf(dx_, dx_, dy_ * dy_);                     \
        if (pj_ != i) { LEX_INSERT(dd_, pj_); }                    \
    }

__global__ __launch_bounds__(THREADS)
void nn_pool_fused(const float2* __restrict__ obs1,
                   const float2* __restrict__ obs2,
                   const float* __restrict__ W,
                   const float* __restrict__ bias,
                   float* __restrict__ out,
                   int n)
{
    extern __shared__ char smem_raw[];
    float2* s_pts  = (float2*)(smem_raw + SM_PTS_OFF);
    int*    s_ofs  = (int*)   (smem_raw + SM_OFS_OFF);   // [NBINS+1]
    int*    s_pid  = (int*)   (smem_raw + SM_PID_OFF);
    int*    s_wsum = (int*)   (smem_raw + SM_WSUM_OFF);

    const int t    = threadIdx.x;
    const int lane = t & 31;
    const int warp = t >> 5;

    // ---------------- per-block grid build (all in SMEM) ----------------
    for (int c = t; c < NBINS + 1; c += THREADS) s_ofs[c] = 0;
    __syncthreads();

    float px[4], py[4];
    int   bins[4];
    #pragma unroll
    for (int k = 0; k < 4; ++k) {
        int p = t + k * THREADS;
        bins[k] = -1;
        if (p < n) {
            float2 v = obs2[p];
            px[k] = v.x; py[k] = v.y;
            int bx = min(NB - 1, max(0, (int)((v.x - BB_MIN) * INVW)));
            int by = min(NB - 1, max(0, (int)((v.y - BB_MIN) * INVW)));
            bins[k] = by * NB + bx;
            atomicAdd(&s_ofs[1 + bins[k]], 1);
        }
    }
    __syncthreads();

    // 2-level warp-shuffle exclusive scan over 4096 counts (4/thread)
    int c4[4];
    #pragma unroll
    for (int k = 0; k < 4; ++k) c4[k] = s_ofs[1 + 4 * t + k];
    int tot = c4[0] + c4[1] + c4[2] + c4[3];
    int incl = tot;
    #pragma unroll
    for (int off = 1; off < 32; off <<= 1) {
        int v = __shfl_up_sync(FULLMASK, incl, off);
        if (lane >= off) incl += v;
    }
    if (lane == 31) s_wsum[warp] = incl;
    __syncthreads();
    if (warp == 0) {
        int v = s_wsum[lane];
        int wi = v;
        #pragma unroll
        for (int off = 1; off < 32; off <<= 1) {
            int u = __shfl_up_sync(FULLMASK, wi, off);
            if (lane >= off) wi += u;
        }
        s_wsum[lane] = wi - v;   // exclusive warp base
    }
    __syncthreads();

    // cursors at s_ofs[1+b]; after scatter table satisfies s_ofs[b] = excl[b]
    int run = s_wsum[warp] + (incl - tot);
    #pragma unroll
    for (int k = 0; k < 4; ++k) {
        s_ofs[1 + 4 * t + k] = run;
        run += c4[k];
    }
    __syncthreads();

    #pragma unroll
    for (int k = 0; k < 4; ++k) {
        if (bins[k] >= 0) {
            int pos = atomicAdd(&s_ofs[1 + bins[k]], 1);
            s_pts[pos] = make_float2(px[k], py[k]);
            s_pid[pos] = t + k * THREADS;
        }
    }
    __syncthreads();

    // ---------------- search: one warp per track, all SMEM ----------------
    const int i = blockIdx.x * TRACKS_PER_BLOCK + warp;
    if (i >= n) return;

    const float2 q = obs2[i];
    const float qx = q.x, qy = q.y;

    const int cx = min(NB - 1, max(0, (int)((qx - BB_MIN) * INVW)));
    const int cy = min(NB - 1, max(0, (int)((qy - BB_MIN) * INVW)));

    float s0 = CUDART_INF_F, s1 = CUDART_INF_F, s2 = CUDART_INF_F, s3 = CUDART_INF_F;
    int   i0 = n, i1 = n, i2 = n, i3 = n;

    // initial 3x3 rect: one cell per lane (9 lanes active)
    int x0 = max(cx - 1, 0), x1 = min(cx + 1, NB - 1);
    int y0 = max(cy - 1, 0), y1 = min(cy + 1, NB - 1);
    {
        const int w = x1 - x0 + 1;
        const int ncells = w * (y1 - y0 + 1);
        if (lane < ncells) {
            int yy = y0 + lane / w, xx = x0 + lane % w;
            int c_ = yy * NB + xx;
            int bg = s_ofs[c_], en = s_ofs[c_ + 1];
            SCAN_SPAN(bg, en);
        }
    }

    while (true) {
        // lower bound on distance to any unprocessed point. Grid-edge sides
        // contribute +inf: all points (incl. clamped outliers) live in bins
        // 0..NB-1, and a clamped outlier lies farther out than its bin's
        // nominal region, so interior-side bounds remain valid lower bounds.
        float bl = (x0 > 0)      ? (qx - (BB_MIN + (float)x0 * CW))       : CUDART_INF_F;
        float br = (x1 < NB - 1) ? ((BB_MIN + (float)(x1 + 1) * CW) - qx) : CUDART_INF_F;
        float bd = (y0 > 0)      ? (qy - (BB_MIN + (float)y0 * CW))       : CUDART_INF_F;
        float bu = (y1 < NB - 1) ? ((BB_MIN + (float)(y1 + 1) * CW) - qy) : CUDART_INF_F;
        float bmin = fminf(fminf(bl, br), fminf(bd, bu));

        if (isinf(bmin)) break;   // rect covers entire grid

        float be = fmaxf(bmin - EPSB, 0.0f);
        float b2 = be * be;
        // exact termination: >=4 candidates (disjoint across lanes) with d2<=b2
        int cnt = (s3 <= b2) ? 4 : (s2 <= b2) ? 3 : (s1 <= b2) ? 2 : (s0 <= b2) ? 1 : 0;
        if (__reduce_add_sync(FULLMASK, cnt) >= 4) break;

        // U = min over lanes of (finite) s3: upper bound on global 4th-best d2
        float U = (s3 < CUDART_INF_F) ? s3 : CUDART_INF_F;
        #pragma unroll
        for (int off = 16; off > 0; off >>= 1)
            U = fminf(U, __shfl_xor_sync(FULLMASK, U, off));

        int nx0, nx1, ny0, ny1;
        if (U < CUDART_INF_F) {
            // jump: final answer lies within radius sqrt(U)+eps of q
            float ru = sqrtf(U) + EPSB;
            nx0 = min(x0, max(0,      (int)((qx - ru - BB_MIN) * INVW)));
            nx1 = max(x1, min(NB - 1, (int)((qx + ru - BB_MIN) * INVW)));
            ny0 = min(y0, max(0,      (int)((qy - ru - BB_MIN) * INVW)));
            ny1 = max(y1, min(NB - 1, (int)((qy + ru - BB_MIN) * INVW)));
            if (nx0 == x0 && nx1 == x1 && ny0 == y0 && ny1 == y1) {
                // fp edge: force progress
                nx0 = max(x0 - 1, 0); nx1 = min(x1 + 1, NB - 1);
                ny0 = max(y0 - 1, 0); ny1 = min(y1 + 1, NB - 1);
            }
        } else {
            // sparse neighborhood: stride 2 across empty space
            nx0 = max(x0 - 2, 0); nx1 = min(x1 + 2, NB - 1);
            ny0 = max(y0 - 2, 0); ny1 = min(y1 + 2, NB - 1);
        }

        // process delta region, one lane per row (rect-height independent)
        for (int yy = ny0 + lane; yy <= ny1; yy += 32) {
            int r = yy * NB;
            if (yy < y0 || yy > y1) {
                int bg = s_ofs[r + nx0], en = s_ofs[r + nx1 + 1];
                SCAN_SPAN(bg, en);
            } else {
                if (nx0 < x0) {
                    int bg = s_ofs[r + nx0], en = s_ofs[r + x0];
                    SCAN_SPAN(bg, en);
                }
                if (nx1 > x1) {
                    int bg = s_ofs[r + x1 + 1], en = s_ofs[r + nx1 + 1];
                    SCAN_SPAN(bg, en);
                }
            }
        }
        x0 = nx0; x1 = nx1; y0 = ny0; y1 = ny1;
    }

    // butterfly merge: every lane ends with identical global top-4
    #pragma unroll
    for (int off = 16; off > 0; off >>= 1) {
        float t0 = __shfl_xor_sync(FULLMASK, s0, off);
        float t1 = __shfl_xor_sync(FULLMASK, s1, off);
        float t2 = __shfl_xor_sync(FULLMASK, s2, off);
        float t3 = __shfl_xor_sync(FULLMASK, s3, off);
        int   u0 = __shfl_xor_sync(FULLMASK, i0, off);
        int   u1 = __shfl_xor_sync(FULLMASK, i1, off);
        int   u2 = __shfl_xor_sync(FULLMASK, i2, off);
        int   u3 = __shfl_xor_sync(FULLMASK, i3, off);
        LEX_INSERT(t0, u0);
        LEX_INSERT(t1, u1);
        LEX_INSERT(t2, u2);
        LEX_INSERT(t3, u3);
    }

    // epilogue: lane = k*8 + e computes out[i][k*8 + e]
    const int k = lane >> 3;
    const int e = lane & 7;
    int nj = (k == 0) ? i0 : (k == 1) ? i1 : (k == 2) ? i2 : i3;
    if (nj >= n) nj = (i == 0) ? 1 : 0;   // degenerate-n safety

    float2 pj  = obs2[nj];
    float2 o1j = obs1[nj];
    float2 o1i = obs1[i];

    float rpx = pj.x - qx;
    float rpy = pj.y - qy;
    float rvx = (pj.x - o1j.x) - (qx - o1i.x);
    float rvy = (pj.y - o1j.y) - (qy - o1i.y);

    float acc = bias[e];
    acc = fmaf(rpx, W[0 * 8 + e], acc);
    acc = fmaf(rpy, W[1 * 8 + e], acc);
    acc = fmaf(rvx, W[2 * 8 + e], acc);
    acc = fmaf(rvy, W[3 * 8 + e], acc);

    out[i * 32 + lane] = fmaxf(acc, 0.0f);
}

extern "C" void kernel_launch(void* const* d_in, const int* in_sizes, int n_in,
                              void* d_out, int out_size) {
    const float2* obs1 = (const float2*)d_in[0];  // [N, 2]
    const float2* obs2 = (const float2*)d_in[1];  // [N, 2]
    const float*  W    = (const float*)d_in[2];   // [4, 8]
    const float*  b    = (const float*)d_in[3];   // [8]
    float* out = (float*)d_out;                    // [N, 32]

    int n = in_sizes[0] / 2;
    if (n > NTRK) n = NTRK;

    static bool attr_set = false;
    if (!attr_set) {
        cudaFuncSetAttribute(nn_pool_fused,
                             cudaFuncAttributeMaxDynamicSharedMemorySize,
                             SM_TOTAL);
        attr_set = true;
    }

    int blocks = (n + TRACKS_PER_BLOCK - 1) / TRACKS_PER_BLOCK;
    nn_pool_fused<<<blocks, THREADS, SM_TOTAL>>>(obs1, obs2, W, b, out, n);
}